// round 12
// baseline (speedup 1.0000x reference)
#include <cuda_runtime.h>

#define BSZ 2
#define SEQ 4096
#define DIM 1024
#define DIM4 256               // float4 per row
#define NCB 128                // chunk-CTAs per batch
#define NBLK (NCB * BSZ)       // 256 total CTAs (co-resident: 2/SM * 148 = 296)
#define EPT (SEQ / 256)        // 16 sequence elems per thread in prep

// ---- global scratch ----
__device__ float4   g_E4[BSZ * NCB * DIM4];   // chunk-end local states
__device__ float4   g_S4[BSZ * NCB * DIM4];   // exclusive incoming state per chunk
__device__ unsigned g_cnt = 0;                // barrier arrival counter
__device__ unsigned g_gen = 0;                // barrier generation

// ---------------------------------------------------------------------------
// Acquire load (no RMW!) — spinning with atomicAdd serialized the L2 atomic
// ALU across 255 pollers (~27cyc each, one address) and starved the release.
__device__ __forceinline__ unsigned ld_acquire_gpu(unsigned* p) {
    unsigned v;
    asm volatile("ld.acquire.gpu.u32 %0, [%1];" : "=r"(v) : "l"(p) : "memory");
    return v;
}

__device__ __forceinline__ void grid_barrier(unsigned* mygen) {
    __syncthreads();
    if (threadIdx.x == 0) {
        __threadfence();
        unsigned a = atomicAdd(&g_cnt, 1u);
        if (a == NBLK - 1) {
            g_cnt = 0u;
            __threadfence();
            atomicExch(&g_gen, *mygen + 1u);   // release
        } else {
            while ((int)(ld_acquire_gpu(&g_gen) - *mygen) <= 0) __nanosleep(64);
        }
        (*mygen)++;
    }
    __syncthreads();
}

// ---------------------------------------------------------------------------
// One fused kernel. grid (NCB, BSZ), 256 threads.
// ---------------------------------------------------------------------------
__global__ void __launch_bounds__(256, 2)
hnet_fused_kernel(const float* __restrict__ hidden,
                  const float* __restrict__ prob,
                  const void* __restrict__ mask_raw,
                  float* __restrict__ out) {
    const int b = blockIdx.y;
    const int c = blockIdx.x;
    const int t = threadIdx.x;
    const int lane = t & 31, wrp = t >> 5;

    __shared__ int   s_pos[SEQ];      // compacted boundary positions (16 KB)
    __shared__ float s_pk [SEQ];      // compacted clipped p (16 KB)
    __shared__ float s_P  [NCB];      // per-chunk decay products (combine only)
    __shared__ int   s_wsum[8];
    __shared__ int   s_nb;
    __shared__ int   s_w;

    unsigned mygen = 0;
    if (t == 0) mygen = ld_acquire_gpu(&g_gen);   // entry generation

    // ================= Phase 1: redundant per-CTA prep =====================
    // mask element-width detect: 4-byte 0/1 values have byte (4j+1)==0 always;
    // 1-byte bool at ~25% density has nonzero there w.p. ~1.
    if (t == 0) s_w = 0;
    __syncthreads();
    {
        const unsigned char* mb = (const unsigned char*)mask_raw;
        int f = 0;
        for (int j = t; j < (BSZ * SEQ) / 4; j += 256) f |= mb[4 * j + 1];
        if (f) s_w = 1;
    }
    __syncthreads();
    const int onebyte = s_w;

    // gather 16 mask bits per thread
    const int base = t * EPT;
    unsigned mbits = 0;
    if (onebyte) {
        const unsigned char* mb = (const unsigned char*)mask_raw + b * SEQ;
        #pragma unroll
        for (int j = 0; j < EPT; j++) if (mb[base + j]) mbits |= (1u << j);
    } else {
        const int* mi = (const int*)mask_raw + b * SEQ;
        #pragma unroll
        for (int j = 0; j < EPT; j++) if (mi[base + j]) mbits |= (1u << j);
    }
    int cnt = __popc(mbits);

    // block inclusive scan of per-thread counts (8 warps)
    int v = cnt;
    #pragma unroll
    for (int o = 1; o < 32; o <<= 1) {
        int u = __shfl_up_sync(0xffffffffu, v, o);
        if (lane >= o) v += u;
    }
    if (lane == 31) s_wsum[wrp] = v;
    __syncthreads();
    if (wrp == 0 && lane < 8) {
        int w = s_wsum[lane];
        #pragma unroll
        for (int o = 1; o < 8; o <<= 1) {
            int u = __shfl_up_sync(0xffu, w, o);
            if (lane >= o) w += u;
        }
        s_wsum[lane] = w;
        if (lane == 7) s_nb = w;
    }
    __syncthreads();

    int run = v - cnt + (wrp ? s_wsum[wrp - 1] : 0);   // exclusive prefix
    const int nb = s_nb;

    {
        const float* pb = prob + b * SEQ;
        #pragma unroll
        for (int j = 0; j < EPT; j++) {
            if (mbits & (1u << j)) {
                const int l = base + j;
                float p = pb[l];
                p = fminf(fmaxf(p, 1e-4f), 0.9999f);
                s_pos[run] = l;
                s_pk [run] = p;
                run++;
            }
        }
    }
    __syncthreads();

    // dynamic chunking: W tokens per CTA so all NCB CTAs are active
    const int W  = (nb + NCB - 1) / NCB;          // <= 32
    const int k0 = c * W;
    const int n  = max(0, min(W, nb - k0));

    const float4* hb = (const float4*)hidden + (size_t)b * SEQ * DIM4 + t;

    // ================= Phase 2: chunk-local scan -> E ======================
    if (n > 0) {
        float4 s = make_float4(0.f, 0.f, 0.f, 0.f);
        for (int j0 = 0; j0 < n; j0 += 8) {
            float4 h[8];
            #pragma unroll
            for (int i = 0; i < 8; i++) {
                const int j = j0 + i;
                h[i] = (j < n) ? __ldg(hb + (size_t)s_pos[k0 + j] * DIM4)
                               : make_float4(0.f, 0.f, 0.f, 0.f);
            }
            #pragma unroll
            for (int i = 0; i < 8; i++) {
                const int j = j0 + i;
                if (j < n) {
                    const float p = s_pk[k0 + j], a = 1.f - p;
                    s.x = fmaf(a, s.x, p * h[i].x);
                    s.y = fmaf(a, s.y, p * h[i].y);
                    s.z = fmaf(a, s.z, p * h[i].z);
                    s.w = fmaf(a, s.w, p * h[i].w);
                }
            }
        }
        g_E4[(size_t)(b * NCB + c) * DIM4 + t] = s;
    }

    grid_barrier(&mygen);   // ---- barrier 1: all E published ----

    // ================= Phase 3: serial combine -> S (c==0 CTAs) ===========
    if (c == 0) {
        const int nc = (nb + W - 1) / W;   // number of non-empty chunks
        // per-chunk scalar products from shared pk
        if (t < nc) {
            const int kk0 = t * W;
            const int nn = min(W, nb - kk0);
            float q = 1.f;
            for (int j = 0; j < nn; j++) q *= (1.f - s_pk[kk0 + j]);
            s_P[t] = q;
        }
        __syncthreads();

        const float4* Eb = g_E4 + (size_t)(b * NCB) * DIM4 + t;
        float4*       Sb = g_S4 + (size_t)(b * NCB) * DIM4 + t;

        float4 S = make_float4(0.f, 0.f, 0.f, 0.f);
        const int G = 8;
        float4 Ebuf[G];
        float  Pbuf[G];
        #pragma unroll
        for (int i = 0; i < G; i++) {
            Ebuf[i] = (i < nc) ? __ldcg(Eb + (size_t)i * DIM4)
                               : make_float4(0.f, 0.f, 0.f, 0.f);
            Pbuf[i] = (i < nc) ? s_P[i] : 1.f;
        }
        for (int g = 0; g < nc; g += G) {
            float4 En[G];
            float  Pn[G];
            #pragma unroll
            for (int i = 0; i < G; i++) {
                const int cc = g + G + i;
                En[i] = (cc < nc) ? __ldcg(Eb + (size_t)cc * DIM4)
                                  : make_float4(0.f, 0.f, 0.f, 0.f);
                Pn[i] = (cc < nc) ? s_P[cc] : 1.f;
            }
            #pragma unroll
            for (int i = 0; i < G; i++) {
                const int cc = g + i;
                if (cc < nc) {
                    Sb[(size_t)cc * DIM4] = S;   // exclusive prefix
                    const float P = Pbuf[i];
                    S.x = fmaf(P, S.x, Ebuf[i].x);
                    S.y = fmaf(P, S.y, Ebuf[i].y);
                    S.z = fmaf(P, S.z, Ebuf[i].z);
                    S.w = fmaf(P, S.w, Ebuf[i].w);
                }
            }
            #pragma unroll
            for (int i = 0; i < G; i++) { Ebuf[i] = En[i]; Pbuf[i] = Pn[i]; }
        }
        __threadfence();
    }

    grid_barrier(&mygen);   // ---- barrier 2: all S published ----

    // ======== Phase 4: seeded rescan + run-expansion to out ===============
    if (n > 0) {
        float4 s = __ldcg(&g_S4[(size_t)(b * NCB + c) * DIM4 + t]);
        float4* ob = (float4*)out + (size_t)b * SEQ * DIM4 + t;

        for (int j0 = 0; j0 < n; j0 += 8) {
            float4 h[8];
            #pragma unroll
            for (int i = 0; i < 8; i++) {
                const int j = j0 + i;
                h[i] = (j < n) ? __ldg(hb + (size_t)s_pos[k0 + j] * DIM4)
                               : make_float4(0.f, 0.f, 0.f, 0.f);
            }
            #pragma unroll
            for (int i = 0; i < 8; i++) {
                const int j = j0 + i;
                if (j < n) {
                    const int k = k0 + j;
                    const float p = s_pk[k], a = 1.f - p;
                    s.x = fmaf(a, s.x, p * h[i].x);
                    s.y = fmaf(a, s.y, p * h[i].y);
                    s.z = fmaf(a, s.z, p * h[i].z);
                    s.w = fmaf(a, s.w, p * h[i].w);
                    const int start = (k == 0) ? 0 : s_pos[k];
                    const int end   = (k + 1 < nb) ? s_pos[k + 1] : SEQ;
                    for (int l = start; l < end; l++)
                        ob[(size_t)l * DIM4] = s;
                }
            }
        }
    }
}

// ---------------------------------------------------------------------------
extern "C" void kernel_launch(void* const* d_in, const int* in_sizes, int n_in,
                              void* d_out, int out_size) {
    const float* hidden = (const float*)d_in[0];
    const float* prob   = (const float*)d_in[1];
    const void*  mask   = d_in[2];
    float* out = (float*)d_out;

    hnet_fused_kernel<<<dim3(NCB, BSZ), 256>>>(hidden, prob, mask, out);
}

// round 14
// speedup vs baseline: 1.3367x; 1.3367x over previous
#include <cuda_runtime.h>

#define BSZ 2
#define SEQ 4096
#define DIM 1024
#define CHUNK 16
#define NCHUNK (SEQ / CHUNK)   // 256

// ---- scratch ----
__device__ int   g_pos[BSZ * SEQ];
__device__ float g_pk [BSZ * SEQ];
__device__ float g_Pc [BSZ * NCHUNK];
__device__ int   g_nb [BSZ];
__device__ float g_E [BSZ * NCHUNK * DIM];
__device__ float g_S [BSZ * NCHUNK * DIM];

// ---------------------------------------------------------------------------
// Kernel 1: mask scan -> pos/pk/nb + per-chunk decay products.
// One block per batch, 1024 threads (4 elems each).
// ---------------------------------------------------------------------------
__global__ void prep_kernel(const float* __restrict__ prob,
                            const void* __restrict__ mask_raw) {
    const int b = blockIdx.x;
    const int t = threadIdx.x;

    __shared__ int   s_w;
    __shared__ int   s_wsum[32];
    __shared__ int   s_total;
    __shared__ float s_pk[SEQ];     // compacted clipped p (16 KB)

    // mask element-width detect (1-byte bool vs 4-byte 0/1)
    if (t == 0) s_w = 0;
    __syncthreads();
    {
        const unsigned char* mb = (const unsigned char*)mask_raw;
        int f = 0;
        for (int j = t; j < (BSZ * SEQ) / 4; j += blockDim.x)
            f |= mb[4 * j + 1];
        if (f) s_w = 1;
    }
    __syncthreads();
    const int onebyte = s_w;

    const int base = t * 4;
    int m[4];
    if (onebyte) {
        const unsigned char* mb = (const unsigned char*)mask_raw + b * SEQ;
        #pragma unroll
        for (int j = 0; j < 4; j++) m[j] = mb[base + j] ? 1 : 0;
    } else {
        const int* mi = (const int*)mask_raw + b * SEQ;
        #pragma unroll
        for (int j = 0; j < 4; j++) m[j] = mi[base + j] ? 1 : 0;
    }
    int cnt = m[0] + m[1] + m[2] + m[3];

    // block inclusive scan of per-thread counts
    int v = cnt;
    const int lane = t & 31, wid = t >> 5;
    #pragma unroll
    for (int o = 1; o < 32; o <<= 1) {
        int u = __shfl_up_sync(0xffffffffu, v, o);
        if (lane >= o) v += u;
    }
    if (lane == 31) s_wsum[wid] = v;
    __syncthreads();
    if (wid == 0) {
        int w = s_wsum[lane];
        #pragma unroll
        for (int o = 1; o < 32; o <<= 1) {
            int u = __shfl_up_sync(0xffffffffu, w, o);
            if (lane >= o) w += u;
        }
        s_wsum[lane] = w;
        if (lane == 31) s_total = w;
    }
    __syncthreads();

    int run = v - cnt + (wid ? s_wsum[wid - 1] : 0);
    const int nb = s_total;
    if (t == 0) g_nb[b] = nb;

    const float* pb = prob + b * SEQ;
    #pragma unroll
    for (int j = 0; j < 4; j++) {
        const int l = base + j;
        if (m[j]) {
            float p = pb[l];
            p = fminf(fmaxf(p, 1e-4f), 0.9999f);
            g_pos[b * SEQ + run] = l;
            g_pk [b * SEQ + run] = p;
            s_pk[run] = p;
            run++;
        }
    }
    __syncthreads();

    // per-chunk decay products: 16-lane shuffle groups over smem
    const int nc = (nb + CHUNK - 1) / CHUNK;
    const int half = lane >> 4;
    const int sub  = lane & 15;
    for (int c = wid * 2 + half; c < nc; c += 64) {
        const int k = c * CHUNK + sub;
        float a = (k < nb) ? (1.f - s_pk[k]) : 1.f;
        #pragma unroll
        for (int o = 8; o > 0; o >>= 1)
            a *= __shfl_xor_sync(0xffffffffu, a, o);
        if (sub == 0) g_Pc[b * NCHUNK + c] = a;
    }
}

// ---------------------------------------------------------------------------
// Kernel 2: chunk-local scan from zero -> chunk-end state g_E.
// grid (DIM/256, NCHUNK, BSZ), 256 threads, scalar channel per thread.
// ---------------------------------------------------------------------------
__global__ void escan_kernel(const float* __restrict__ hidden) {
    const int b = blockIdx.z, c = blockIdx.y;
    const int d = blockIdx.x * 256 + threadIdx.x;
    const int nb = g_nb[b];
    const int k0 = c * CHUNK;
    if (k0 >= nb) return;
    const int n = min(CHUNK, nb - k0);

    __shared__ int   spos[CHUNK];
    __shared__ float spk [CHUNK];
    if (threadIdx.x < n) {
        spos[threadIdx.x] = g_pos[b * SEQ + k0 + threadIdx.x];
        spk [threadIdx.x] = g_pk [b * SEQ + k0 + threadIdx.x];
    }
    __syncthreads();

    const float* hb = hidden + (size_t)b * SEQ * DIM + d;
    float h[CHUNK];
    #pragma unroll
    for (int j = 0; j < CHUNK; j++)
        h[j] = (j < n) ? __ldg(hb + (size_t)spos[j] * DIM) : 0.f;

    float s = 0.f;
    #pragma unroll
    for (int j = 0; j < CHUNK; j++) {
        if (j < n) {
            const float p = spk[j];
            s = fmaf(1.f - p, s, p * h[j]);
        }
    }
    g_E[(size_t)(b * NCHUNK + c) * DIM + d] = s;
}

// ---------------------------------------------------------------------------
// Kernel 3: serial combine across chunks -> g_S (exclusive incoming states).
// grid (DIM/256, BSZ), 256 threads scalar, 16-deep double-buffered prefetch.
// ---------------------------------------------------------------------------
__global__ void combine_kernel() {
    const int b = blockIdx.y;
    const int d = blockIdx.x * 256 + threadIdx.x;
    const int nb = g_nb[b];
    const int nc = (nb + CHUNK - 1) / CHUNK;

    const float* Eb = g_E + (size_t)(b * NCHUNK) * DIM + d;
    const float* Pb = g_Pc + b * NCHUNK;
    float*       Sb = g_S + (size_t)(b * NCHUNK) * DIM + d;

    float s = 0.f;
    const int G = 16;
    float Ebuf[G], Pbuf[G];
    #pragma unroll
    for (int j = 0; j < G; j++) {
        Ebuf[j] = (j < nc) ? Eb[(size_t)j * DIM] : 0.f;
        Pbuf[j] = (j < nc) ? Pb[j] : 1.f;
    }
    for (int g = 0; g < NCHUNK && g < nc; g += G) {
        float En[G], Pn[G];
        #pragma unroll
        for (int j = 0; j < G; j++) {
            const int cc = g + G + j;
            En[j] = (cc < nc) ? Eb[(size_t)cc * DIM] : 0.f;
            Pn[j] = (cc < nc) ? Pb[cc] : 1.f;
        }
        #pragma unroll
        for (int j = 0; j < G; j++) {
            const int cc = g + j;
            if (cc < nc) {
                Sb[(size_t)cc * DIM] = s;
                s = fmaf(Pbuf[j], s, Ebuf[j]);
            }
        }
        #pragma unroll
        for (int j = 0; j < G; j++) { Ebuf[j] = En[j]; Pbuf[j] = Pn[j]; }
    }
}

// ---------------------------------------------------------------------------
// Kernel 4: seeded rescan + run-expansion to out.
// grid (DIM/256, NCHUNK, BSZ) = 2048 CTAs, 256 threads, scalar channel.
// ---------------------------------------------------------------------------
__global__ void fused_out_kernel(const float* __restrict__ hidden,
                                 float* __restrict__ out) {
    const int b = blockIdx.z, c = blockIdx.y;
    const int d = blockIdx.x * 256 + threadIdx.x;
    const int nb = g_nb[b];
    const int k0 = c * CHUNK;
    if (k0 >= nb) return;
    const int n = min(CHUNK, nb - k0);

    __shared__ int   spos[CHUNK + 1];
    __shared__ float spk [CHUNK];
    if (threadIdx.x <= n) {
        const int kk = k0 + threadIdx.x;
        spos[threadIdx.x] = (kk < nb) ? g_pos[b * SEQ + kk] : SEQ;
    }
    if (threadIdx.x < n)
        spk[threadIdx.x] = g_pk[b * SEQ + k0 + threadIdx.x];
    __syncthreads();

    const float* hb = hidden + (size_t)b * SEQ * DIM + d;
    float h[CHUNK];
    #pragma unroll
    for (int j = 0; j < CHUNK; j++)
        h[j] = (j < n) ? __ldg(hb + (size_t)spos[j] * DIM) : 0.f;

    float s = g_S[(size_t)(b * NCHUNK + c) * DIM + d];
    float* ob = out + (size_t)b * SEQ * DIM + d;

    #pragma unroll
    for (int j = 0; j < CHUNK; j++) {
        if (j < n) {
            const float p = spk[j];
            s = fmaf(1.f - p, s, p * h[j]);
            const int start = (k0 + j == 0) ? 0 : spos[j];
            const int end = spos[j + 1];
            for (int l = start; l < end; l++)
                ob[(size_t)l * DIM] = s;
        }
    }
}

// ---------------------------------------------------------------------------
extern "C" void kernel_launch(void* const* d_in, const int* in_sizes, int n_in,
                              void* d_out, int out_size) {
    const float* hidden = (const float*)d_in[0];
    const float* prob   = (const float*)d_in[1];
    const void*  mask   = d_in[2];
    float* out = (float*)d_out;

    prep_kernel<<<BSZ, 1024>>>(prob, mask);
    escan_kernel<<<dim3(DIM / 256, NCHUNK, BSZ), 256>>>(hidden);
    combine_kernel<<<dim3(DIM / 256, BSZ), 256>>>();
    fused_out_kernel<<<dim3(DIM / 256, NCHUNK, BSZ), 256>>>(hidden, out);
}